// round 10
// baseline (speedup 1.0000x reference)
#include <cuda_runtime.h>
#include <cstdint>

// db2 inverse DWT (synthesis), polyphase. 2 input cols x 1 row per thread.
// Block = 512 threads covering 2 input rows -> 4 contiguous output rows,
// staged in smem (16KB) and written with ONE cp.async.bulk per block.
// Horizontal halo via warp shuffle; vertical halo via L1/L2.
// x: [32, 512, 512, 4] NHWC f32  ->  y: [32, 1024, 1024, 1] f32

#define IN_H 512
#define IN_W 512
#define IN_B 32

struct F8 { float4 a, b; };

__device__ __forceinline__ F8 ldg8(const float4* p) {
    unsigned r0,r1,r2,r3,r4,r5,r6,r7;
    asm volatile("ld.global.nc.v8.b32 {%0,%1,%2,%3,%4,%5,%6,%7}, [%8];"
                 : "=r"(r0), "=r"(r1), "=r"(r2), "=r"(r3),
                   "=r"(r4), "=r"(r5), "=r"(r6), "=r"(r7)
                 : "l"(p));
    F8 v;
    v.a = make_float4(__uint_as_float(r0), __uint_as_float(r1),
                      __uint_as_float(r2), __uint_as_float(r3));
    v.b = make_float4(__uint_as_float(r4), __uint_as_float(r5),
                      __uint_as_float(r6), __uint_as_float(r7));
    return v;
}

__device__ __forceinline__ float4 shfl_down_f4(float4 v) {
    float4 r;
    r.x = __shfl_down_sync(0xffffffffu, v.x, 1);
    r.y = __shfl_down_sync(0xffffffffu, v.y, 1);
    r.z = __shfl_down_sync(0xffffffffu, v.z, 1);
    r.w = __shfl_down_sync(0xffffffffu, v.w, 1);
    return r;
}

__device__ __forceinline__ void quad2x2(
    const float4& v00, const float4& v01,
    const float4& v10, const float4& v11,
    const float L[2][2], const float G[2][2],
    float out[2][2])
{
    float a0[2] = { v00.x + v00.y, v10.x + v10.y };
    float a1[2] = { v01.x + v01.y, v11.x + v11.y };
    float z0[2] = { v00.z, v10.z };
    float z1[2] = { v01.z, v11.z };
    float w0[2] = { v00.w, v10.w };
    float w1[2] = { v01.w, v11.w };

    float r_az[2][2], r_w[2][2];
#pragma unroll
    for (int dv = 0; dv < 2; ++dv) {
#pragma unroll
        for (int ah = 0; ah < 2; ++ah) {
            float r = L[ah][0] * a0[dv];
            r = fmaf(L[ah][1], a1[dv], r);
            r = fmaf(G[ah][0], z0[dv], r);
            r = fmaf(G[ah][1], z1[dv], r);
            r_az[dv][ah] = r;
            r_w[dv][ah] = fmaf(G[ah][0], w0[dv], G[ah][1] * w1[dv]);
        }
    }
#pragma unroll
    for (int av = 0; av < 2; ++av) {
#pragma unroll
        for (int ah = 0; ah < 2; ++ah) {
            float r = L[av][0] * r_az[0][ah];
            r = fmaf(L[av][1], r_az[1][ah], r);
            r = fmaf(G[av][0], r_w[0][ah], r);
            r = fmaf(G[av][1], r_w[1][ah], r);
            out[av][ah] = r;
        }
    }
}

__global__ __launch_bounds__(512)
void idwt_db2_kernel(const float4* __restrict__ x, float4* __restrict__ y) {
    __shared__ float4 buf[1024];           // 4 output rows, 16KB, gmem-contiguous

    const int tid  = threadIdx.x;          // 0..511
    const int u    = tid & 255;            // col pair 0..255
    const int rr   = tid >> 8;             // 0..1 (row within block)
    const int s    = 2 * blockIdx.x + rr;  // input row 0..511
    const int b    = blockIdx.z;           // 0..31
    const int lane = tid & 31;

    const float h0 = 0.48296291314469025f;
    const float h1 = 0.83651630373780790f;
    const float h2 = 0.22414386804185735f;
    const float h3 = -0.12940952255092145f;
    const float L[2][2] = { { h2,  h0 }, {  h3,  h1 } };
    const float G[2][2] = { { h1,  h3 }, { -h0, -h2 } };

    const int t0 = 2 * u;
    const int t2 = min(t0 + 2, IN_W - 1);
    const int s1 = min(s + 1, IN_H - 1);

    const size_t r0 = ((size_t)b * IN_H + s ) * IN_W;
    const size_t r1 = ((size_t)b * IN_H + s1) * IN_W;

    float4 Ah31, Bh31;
    if (lane == 31) {
        Ah31 = __ldg(&x[r0 + t2]);
        Bh31 = __ldg(&x[r1 + t2]);
    }
    const F8 A = ldg8(&x[r0 + t0]);
    const F8 B = ldg8(&x[r1 + t0]);

    float4 Ah = shfl_down_f4(A.a);
    float4 Bh = shfl_down_f4(B.a);
    if (lane == 31) { Ah = Ah31; Bh = Bh31; }

    float oA[2][2], oB[2][2];
    quad2x2(A.a, A.b, B.a, B.b, L, G, oA);   // out cols 4u..4u+1
    quad2x2(A.b, Ah,  B.b, Bh,  L, G, oB);   // out cols 4u+2..4u+3

    // rr=0 -> out rows 0,1 of the 4-row group; rr=1 -> rows 2,3
    buf[rr * 512 + u]       = make_float4(oA[0][0], oA[0][1], oB[0][0], oB[0][1]);
    buf[rr * 512 + 256 + u] = make_float4(oA[1][0], oA[1][1], oB[1][0], oB[1][1]);
    __syncthreads();

    if (tid == 0) {
        uint32_t saddr;
        asm("{ .reg .u64 t; cvta.to.shared.u64 t, %1; cvt.u32.u64 %0, t; }"
            : "=r"(saddr) : "l"(buf));
        const float4* gdst = &y[((size_t)b * 1024 + (size_t)4 * blockIdx.x) * 256];
        asm volatile("fence.proxy.async.shared::cta;" ::: "memory");
        asm volatile("cp.async.bulk.global.shared::cta.bulk_group [%0], [%1], %2;"
                     :: "l"(gdst), "r"(saddr), "r"(16384) : "memory");
        asm volatile("cp.async.bulk.commit_group;" ::: "memory");
        asm volatile("cp.async.bulk.wait_group.read 0;" ::: "memory");
    }
}

extern "C" void kernel_launch(void* const* d_in, const int* in_sizes, int n_in,
                              void* d_out, int out_size) {
    const float4* x = (const float4*)d_in[0];
    float4* y = (float4*)d_out;
    dim3 block(512, 1, 1);
    dim3 grid(IN_H / 2, 1, IN_B);
    idwt_db2_kernel<<<grid, block>>>(x, y);
}

// round 11
// speedup vs baseline: 1.0007x; 1.0007x over previous
#include <cuda_runtime.h>
#include <cstdint>

// db2 inverse DWT (synthesis), polyphase. 2 input cols x 1 row per thread,
// block = one input row (256 threads). Horizontal halo via warp shuffle.
// Output staged in smem (8KB) and written with one cp.async.bulk per block,
// with an L2::evict_first cache policy so dirty output lines drain to DRAM
// during the kernel (overlapping idle DRAM slots) instead of in a serialized
// tail before the next replay.
// x: [32, 512, 512, 4] NHWC f32  ->  y: [32, 1024, 1024, 1] f32

#define IN_H 512
#define IN_W 512
#define IN_B 32

struct F8 { float4 a, b; };

__device__ __forceinline__ F8 ldg8(const float4* p) {
    unsigned r0,r1,r2,r3,r4,r5,r6,r7;
    asm volatile("ld.global.nc.v8.b32 {%0,%1,%2,%3,%4,%5,%6,%7}, [%8];"
                 : "=r"(r0), "=r"(r1), "=r"(r2), "=r"(r3),
                   "=r"(r4), "=r"(r5), "=r"(r6), "=r"(r7)
                 : "l"(p));
    F8 v;
    v.a = make_float4(__uint_as_float(r0), __uint_as_float(r1),
                      __uint_as_float(r2), __uint_as_float(r3));
    v.b = make_float4(__uint_as_float(r4), __uint_as_float(r5),
                      __uint_as_float(r6), __uint_as_float(r7));
    return v;
}

__device__ __forceinline__ float4 shfl_down_f4(float4 v) {
    float4 r;
    r.x = __shfl_down_sync(0xffffffffu, v.x, 1);
    r.y = __shfl_down_sync(0xffffffffu, v.y, 1);
    r.z = __shfl_down_sync(0xffffffffu, v.z, 1);
    r.w = __shfl_down_sync(0xffffffffu, v.w, 1);
    return r;
}

__device__ __forceinline__ void quad2x2(
    const float4& v00, const float4& v01,
    const float4& v10, const float4& v11,
    const float L[2][2], const float G[2][2],
    float out[2][2])
{
    float a0[2] = { v00.x + v00.y, v10.x + v10.y };
    float a1[2] = { v01.x + v01.y, v11.x + v11.y };
    float z0[2] = { v00.z, v10.z };
    float z1[2] = { v01.z, v11.z };
    float w0[2] = { v00.w, v10.w };
    float w1[2] = { v01.w, v11.w };

    float r_az[2][2], r_w[2][2];
#pragma unroll
    for (int dv = 0; dv < 2; ++dv) {
#pragma unroll
        for (int ah = 0; ah < 2; ++ah) {
            float r = L[ah][0] * a0[dv];
            r = fmaf(L[ah][1], a1[dv], r);
            r = fmaf(G[ah][0], z0[dv], r);
            r = fmaf(G[ah][1], z1[dv], r);
            r_az[dv][ah] = r;
            r_w[dv][ah] = fmaf(G[ah][0], w0[dv], G[ah][1] * w1[dv]);
        }
    }
#pragma unroll
    for (int av = 0; av < 2; ++av) {
#pragma unroll
        for (int ah = 0; ah < 2; ++ah) {
            float r = L[av][0] * r_az[0][ah];
            r = fmaf(L[av][1], r_az[1][ah], r);
            r = fmaf(G[av][0], r_w[0][ah], r);
            r = fmaf(G[av][1], r_w[1][ah], r);
            out[av][ah] = r;
        }
    }
}

__global__ __launch_bounds__(256)
void idwt_db2_kernel(const float4* __restrict__ x, float4* __restrict__ y) {
    __shared__ float4 buf[512];            // 2 output rows, 8KB, gmem-contiguous

    const int u    = threadIdx.x;          // 0..255 (col pair); block = one row
    const int s    = blockIdx.x;           // 0..511
    const int b    = blockIdx.z;           // 0..31
    const int lane = u & 31;

    const float h0 = 0.48296291314469025f;
    const float h1 = 0.83651630373780790f;
    const float h2 = 0.22414386804185735f;
    const float h3 = -0.12940952255092145f;
    const float L[2][2] = { { h2,  h0 }, {  h3,  h1 } };
    const float G[2][2] = { { h1,  h3 }, { -h0, -h2 } };

    const int t0 = 2 * u;
    const int t2 = min(t0 + 2, IN_W - 1);
    const int s1 = min(s + 1, IN_H - 1);

    const size_t r0 = ((size_t)b * IN_H + s ) * IN_W;
    const size_t r1 = ((size_t)b * IN_H + s1) * IN_W;

    float4 Ah31, Bh31;
    if (lane == 31) {
        Ah31 = __ldg(&x[r0 + t2]);
        Bh31 = __ldg(&x[r1 + t2]);
    }
    const F8 A = ldg8(&x[r0 + t0]);
    const F8 B = ldg8(&x[r1 + t0]);

    float4 Ah = shfl_down_f4(A.a);
    float4 Bh = shfl_down_f4(B.a);
    if (lane == 31) { Ah = Ah31; Bh = Bh31; }

    float oA[2][2], oB[2][2];
    quad2x2(A.a, A.b, B.a, B.b, L, G, oA);   // out cols 4u..4u+1
    quad2x2(A.b, Ah,  B.b, Bh,  L, G, oB);   // out cols 4u+2..4u+3

    buf[u]       = make_float4(oA[0][0], oA[0][1], oB[0][0], oB[0][1]);
    buf[u + 256] = make_float4(oA[1][0], oA[1][1], oB[1][0], oB[1][1]);
    __syncthreads();

    if (u == 0) {
        uint32_t saddr;
        asm("{ .reg .u64 t; cvta.to.shared.u64 t, %1; cvt.u32.u64 %0, t; }"
            : "=r"(saddr) : "l"(buf));
        const float4* gdst = &y[((size_t)b * 1024 + 2 * s) * 256];
        asm volatile("fence.proxy.async.shared::cta;" ::: "memory");
        asm volatile(
            "{\n\t"
            ".reg .b64 pol;\n\t"
            "createpolicy.fractional.L2::evict_first.b64 pol, 1.0;\n\t"
            "cp.async.bulk.global.shared::cta.bulk_group.L2::cache_hint "
            "[%0], [%1], %2, pol;\n\t"
            "}"
            :: "l"(gdst), "r"(saddr), "r"(8192) : "memory");
        asm volatile("cp.async.bulk.commit_group;" ::: "memory");
        asm volatile("cp.async.bulk.wait_group.read 0;" ::: "memory");
    }
}

extern "C" void kernel_launch(void* const* d_in, const int* in_sizes, int n_in,
                              void* d_out, int out_size) {
    const float4* x = (const float4*)d_in[0];
    float4* y = (float4*)d_out;
    dim3 block(256, 1, 1);
    dim3 grid(IN_H, 1, IN_B);
    idwt_db2_kernel<<<grid, block>>>(x, y);
}